// round 9
// baseline (speedup 1.0000x reference)
#include <cuda_runtime.h>
#include <cuda_fp16.h>
#include <cstdint>
#include <cstddef>

#define B_ 2
#define N_ 50000
#define E_ 500000
#define D_ 128
#define O_ 128
#define K_ 384
#define M_ (B_*N_)
#define MPAD_ (M_ + 128)

// ---------------------------------------------------------------------------
// Device scratch
// ---------------------------------------------------------------------------
__device__ __half g_A[(size_t)MPAD_ * 256];    // fp16 [inv*XS | inv*EA] (51.3MB)
__device__ __half g_xh2[(size_t)N_ * B_ * D_]; // fp16 x interleaved [n][b][d] (25.6MB)
__device__ int   g_icnt[N_];                   // in-degree counts
__device__ int   g_off[N_ + 1];                // CSR offsets by dst
__device__ int   g_pos[N_];                    // fill cursor
__device__ int2  g_edge[E_];                   // (src, edge id) sorted by dst
__device__ __half g_Bhi[O_ * K_];              // (W_msg@W_upd)^T hi, [o][k]
__device__ __half g_Blo[O_ * K_];              // (W_msg@W_upd)^T lo (residual)
__device__ float g_bmu[O_];                    // b_msg @ W_upd

// ---------------------------------------------------------------------------
// PTX helpers
// ---------------------------------------------------------------------------
#define MMA_F16(d, a, b)                                                      \
    asm volatile("mma.sync.aligned.m16n8k16.row.col.f32.f16.f16.f32 "         \
        "{%0,%1,%2,%3}, {%4,%5,%6,%7}, {%8,%9}, {%0,%1,%2,%3};"               \
        : "+f"((d)[0]), "+f"((d)[1]), "+f"((d)[2]), "+f"((d)[3])              \
        : "r"((a)[0]), "r"((a)[1]), "r"((a)[2]), "r"((a)[3]),                 \
          "r"((b)[0]), "r"((b)[1]))

#define CP_ASYNC16(dst_u32, src_ptr)                                          \
    asm volatile("cp.async.cg.shared.global [%0], [%1], 16;"                  \
                 :: "r"(dst_u32), "l"(src_ptr))
#define CP_COMMIT() asm volatile("cp.async.commit_group;" ::: "memory")
#define CP_WAIT(n)  asm volatile("cp.async.wait_group %0;" :: "n"(n) : "memory")

__device__ __forceinline__ uint32_t smem_u32(const void* p) {
    uint32_t a;
    asm("{ .reg .u64 t; cvta.to.shared.u64 t, %1; cvt.u32.u64 %0, t; }"
        : "=r"(a) : "l"(p));
    return a;
}

__device__ __forceinline__ uint4 cvt8_h(float4 f0, float4 f1) {
    uint32_t p0, p1, p2, p3;
    asm("cvt.rn.f16x2.f32 %0, %2, %1;" : "=r"(p0) : "f"(f0.x), "f"(f0.y));
    asm("cvt.rn.f16x2.f32 %0, %2, %1;" : "=r"(p1) : "f"(f0.z), "f"(f0.w));
    asm("cvt.rn.f16x2.f32 %0, %2, %1;" : "=r"(p2) : "f"(f1.x), "f"(f1.y));
    asm("cvt.rn.f16x2.f32 %0, %2, %1;" : "=r"(p3) : "f"(f1.z), "f"(f1.w));
    return make_uint4(p0, p1, p2, p3);
}
__device__ __forceinline__ uint2 cvt4_h(float4 f) {
    uint32_t p0, p1;
    asm("cvt.rn.f16x2.f32 %0, %2, %1;" : "=r"(p0) : "f"(f.x), "f"(f.y));
    asm("cvt.rn.f16x2.f32 %0, %2, %1;" : "=r"(p1) : "f"(f.z), "f"(f.w));
    return make_uint2(p0, p1);
}

// ---------------------------------------------------------------------------
// x -> fp16 interleaved copy: g_xh2[(n*2+b)*128 + d] = fp16(x[b][n][d])
// ---------------------------------------------------------------------------
__global__ void x_to_h(const float* __restrict__ x) {
    const size_t nc = (size_t)B_ * N_ * 16;     // uint4 chunks
    size_t i = (size_t)blockIdx.x * blockDim.x + threadIdx.x;
    if (i < nc) {
        size_t row = i >> 4;
        int c = (int)(i & 15);
        int b = (row >= (size_t)N_) ? 1 : 0;
        size_t n = row - (size_t)b * N_;
        float4 f0 = reinterpret_cast<const float4*>(x)[row * 32 + c * 2];
        float4 f1 = reinterpret_cast<const float4*>(x)[row * 32 + c * 2 + 1];
        reinterpret_cast<uint4*>(g_xh2)[(n * 2 + b) * 16 + c] = cvt8_h(f0, f1);
    }
}

// ---------------------------------------------------------------------------
// CSR build (unchanged)
// ---------------------------------------------------------------------------
__global__ void zero_icnt() {
    int i = blockIdx.x * blockDim.x + threadIdx.x;
    if (i < N_) g_icnt[i] = 0;
}

__global__ void hist_kernel(const int* __restrict__ ei) {
    int e = blockIdx.x * blockDim.x + threadIdx.x;
    if (e < E_) atomicAdd(&g_icnt[ei[E_ + e]], 1);
}

__global__ void scan_kernel() {
    __shared__ int ssum[1024];
    const int CH = (N_ + 1023) / 1024;
    int t = threadIdx.x;
    int beg = t * CH, end = min(beg + CH, N_);
    int s = 0;
    for (int i = beg; i < end; ++i) s += g_icnt[i];
    ssum[t] = s;
    __syncthreads();
    for (int off = 1; off < 1024; off <<= 1) {
        int v = (t >= off) ? ssum[t - off] : 0;
        __syncthreads();
        ssum[t] += v;
        __syncthreads();
    }
    int run = (t == 0) ? 0 : ssum[t - 1];
    for (int i = beg; i < end; ++i) {
        g_off[i] = run;
        g_pos[i] = run;
        run += g_icnt[i];
    }
    if (t == 1023) g_off[N_] = run;
}

__global__ void fill_kernel(const int* __restrict__ ei) {
    int e = blockIdx.x * blockDim.x + threadIdx.x;
    if (e < E_) {
        int dst = ei[E_ + e];
        int p = atomicAdd(&g_pos[dst], 1);
        g_edge[p] = make_int2(ei[e], e);
    }
}

// ---------------------------------------------------------------------------
// Aggregation: warp per node. Per edge: ONE 512B x row (both batches, uint4
// per lane) + one 512B ea row (float4 per lane). fp32 accumulate. Writes
// g_A[r][0:128)=inv*XS, g_A[r][128:256)=inv*EA for both batch rows.
// ---------------------------------------------------------------------------
__device__ __forceinline__ void add_h4u(float4& a, uint32_t lo, uint32_t hi) {
    float2 l = __half22float2(*reinterpret_cast<__half2*>(&lo));
    float2 h = __half22float2(*reinterpret_cast<__half2*>(&hi));
    a.x += l.x; a.y += l.y; a.z += h.x; a.w += h.y;
}
__device__ __forceinline__ float4 scale4(float4 a, float s) {
    return make_float4(a.x * s, a.y * s, a.z * s, a.w * s);
}

__global__ void aggregate(const float* __restrict__ ea) {
    int n = (int)(((size_t)blockIdx.x * blockDim.x + threadIdx.x) >> 5);
    int lane = threadIdx.x & 31;
    if (n >= N_) return;

    int j0 = g_off[n], j1 = g_off[n + 1];
    float4 ae = make_float4(0.f, 0.f, 0.f, 0.f);
    float4 xa = ae, xb = ae;            // 8 x-channels per lane
    float4 ae2 = ae, xa2 = ae, xb2 = ae;

    int j = j0;
    for (; j + 2 <= j1; j += 2) {
        int2 p0 = g_edge[j];
        int2 p1 = g_edge[j + 1];
        float4 v0 = reinterpret_cast<const float4*>(ea + (size_t)p0.y * D_)[lane];
        float4 v1 = reinterpret_cast<const float4*>(ea + (size_t)p1.y * D_)[lane];
        uint4 u0 = reinterpret_cast<const uint4*>(g_xh2 + (size_t)p0.x * 256)[lane];
        uint4 u1 = reinterpret_cast<const uint4*>(g_xh2 + (size_t)p1.x * 256)[lane];
        ae.x += v0.x; ae.y += v0.y; ae.z += v0.z; ae.w += v0.w;
        ae2.x += v1.x; ae2.y += v1.y; ae2.z += v1.z; ae2.w += v1.w;
        add_h4u(xa, u0.x, u0.y); add_h4u(xb, u0.z, u0.w);
        add_h4u(xa2, u1.x, u1.y); add_h4u(xb2, u1.z, u1.w);
    }
    if (j < j1) {
        int2 p0 = g_edge[j];
        float4 v0 = reinterpret_cast<const float4*>(ea + (size_t)p0.y * D_)[lane];
        uint4 u0 = reinterpret_cast<const uint4*>(g_xh2 + (size_t)p0.x * 256)[lane];
        ae.x += v0.x; ae.y += v0.y; ae.z += v0.z; ae.w += v0.w;
        add_h4u(xa, u0.x, u0.y); add_h4u(xb, u0.z, u0.w);
    }
    ae.x += ae2.x; ae.y += ae2.y; ae.z += ae2.z; ae.w += ae2.w;
    xa.x += xa2.x; xa.y += xa2.y; xa.z += xa2.z; xa.w += xa2.w;
    xb.x += xb2.x; xb.y += xb2.y; xb.z += xb2.z; xb.w += xb2.w;

    int deg = j1 - j0;
    float inv = 1.0f / (float)max(deg, 1);

    // XS: lanes 0-15 -> batch0 row, channels 8*lane; lanes 16-31 -> batch1.
    uint4 hx = cvt8_h(scale4(xa, inv), scale4(xb, inv));
    size_t rrow = (lane < 16) ? (size_t)n : ((size_t)N_ + n);
    int l8 = (lane & 15) * 8;
    *reinterpret_cast<uint4*>(g_A + rrow * 256 + l8) = hx;

    // EA: channel 4*lane, identical in both batch rows.
    uint2 he = cvt4_h(scale4(ae, inv));
    *reinterpret_cast<uint2*>(g_A + (size_t)n * 256 + 128 + lane * 4) = he;
    *reinterpret_cast<uint2*>(g_A + ((size_t)N_ + n) * 256 + 128 + lane * 4) = he;
}

// ---------------------------------------------------------------------------
// Combined weights, transposed + fp16 hi/lo split (unchanged)
// ---------------------------------------------------------------------------
__global__ void combine_weights(const float* __restrict__ Wm,
                                const float* __restrict__ Wu,
                                const float* __restrict__ bm) {
    int idx = blockIdx.x * blockDim.x + threadIdx.x;
    if (idx < K_ * O_) {
        int o = idx / K_;
        int k = idx - o * K_;
        float s = 0.f;
        #pragma unroll 8
        for (int j = 0; j < O_; ++j)
            s = fmaf(Wm[k * O_ + j], Wu[j * O_ + o], s);
        __half hb = __float2half_rn(s);
        float r = s - __half2float(hb);
        g_Bhi[idx] = hb;
        g_Blo[idx] = __float2half_rn(r);
    }
    if (idx < O_) {
        float s = 0.f;
        for (int j = 0; j < O_; ++j)
            s = fmaf(bm[j], Wu[j * O_ + idx], s);
        g_bmu[idx] = s;
    }
}

// ---------------------------------------------------------------------------
// HGEMM: out[r] = cc*( A[r]@(Bhi+Blo)^T + bmu ) + bu
// A k-layout: [0:128)=g_A XS | [128:256)=g_xh2 | [256:384)=g_A EA.
// CTA 128x128, BK=32, 256 thr (4m x 2n warps), warp tile 32x64,
// 3-stage cp.async pipeline (92KB smem, 2 CTAs/SM).
// ---------------------------------------------------------------------------
#define STR_ 40                       // fp16 per smem row
#define TB_  (128 * STR_ * 2)         // bytes per tile (10240)
#define AOF(s)  ((s) * 3 * TB_)
#define BHOF(s) ((s) * 3 * TB_ + TB_)
#define BLOF(s) ((s) * 3 * TB_ + 2 * TB_)
#define SMEM_DYN_ (9 * TB_)           // 92160

__global__ __launch_bounds__(256, 2)
void fused_gemm_mma(const float* __restrict__ bu,
                    float* __restrict__ out)
{
    extern __shared__ char sm[];
    __shared__ float cc_s[128], bmu_s[128], bu_s[128];

    const int tid  = threadIdx.x;
    const int lane = tid & 31;
    const int wid  = tid >> 5;
    const int r0   = blockIdx.x * 128;
    const int wm   = wid >> 1;        // 0..3
    const int wn   = wid & 1;         // 0..1
    const int g    = lane >> 2;       // 0..7
    const int tq   = lane & 3;        // 0..3

    const uint32_t smb = smem_u32(sm);

    if (tid < 128) {
        int r = r0 + tid;
        float cc = 0.f;
        if (r < M_) {
            int n = (r >= N_) ? (r - N_) : r;
            cc = (g_icnt[n] > 0) ? 1.f : 0.f;
        }
        cc_s[tid]  = cc;
        bmu_s[tid] = g_bmu[tid];
        bu_s[tid]  = bu[tid];
    }

    auto issue = [&](int kb, int bf) {
        const uint32_t ao = smb + AOF(bf), ho = smb + BHOF(bf), lo = smb + BLOF(bf);
        #pragma unroll
        for (int t = 0; t < 2; ++t) {
            int c    = tid + t * 256;
            int row  = c >> 2;
            int col8 = (c & 3) * 8;
            uint32_t so = (uint32_t)((row * STR_ + col8) * 2);
            const __half* asrc;
            int r = r0 + row;
            if (kb < 128) {
                asrc = g_A + (size_t)r * 256 + kb + col8;
            } else if (kb < 256) {
                int rc = (r < M_) ? r : (M_ - 1);
                int b  = (rc >= N_) ? 1 : 0;
                int n  = rc - b * N_;
                asrc = g_xh2 + ((size_t)n * 2 + b) * 128 + (kb - 128) + col8;
            } else {
                asrc = g_A + (size_t)r * 256 + (kb - 128) + col8;
            }
            CP_ASYNC16(ao + so, asrc);
            CP_ASYNC16(ho + so, g_Bhi + (size_t)row * K_ + kb + col8);
            CP_ASYNC16(lo + so, g_Blo + (size_t)row * K_ + kb + col8);
        }
        CP_COMMIT();
    };

    float acc[2][8][4];
    #pragma unroll
    for (int i = 0; i < 2; ++i)
        #pragma unroll
        for (int j = 0; j < 8; ++j)
            #pragma unroll
            for (int c = 0; c < 4; ++c) acc[i][j][c] = 0.f;

    issue(0, 0);
    issue(32, 1);

    const int NT = K_ / 32;  // 12
    for (int kt = 0; kt < NT; ++kt) {
        const int cur = kt % 3;
        if (kt + 2 < NT) {
            issue((kt + 2) * 32, (kt + 2) % 3);
            CP_WAIT(2);
        } else if (kt + 1 < NT) {
            CP_WAIT(1);
        } else {
            CP_WAIT(0);
        }
        __syncthreads();

        const char* Ab  = sm + AOF(cur);
        const char* Bhb = sm + BHOF(cur);
        const char* Blb = sm + BLOF(cur);

        #pragma unroll
        for (int ks = 0; ks < 2; ++ks) {
            const int k0 = ks * 16;
            uint32_t ah[2][4], bh[8][2], bl[8][2];
            #pragma unroll
            for (int i = 0; i < 2; ++i) {
                int base = ((wm * 32 + i * 16 + g) * STR_ + k0 + tq * 2) * 2;
                ah[i][0] = *reinterpret_cast<const uint32_t*>(Ab + base);
                ah[i][1] = *reinterpret_cast<const uint32_t*>(Ab + base + 8 * STR_ * 2);
                ah[i][2] = *reinterpret_cast<const uint32_t*>(Ab + base + 16);
                ah[i][3] = *reinterpret_cast<const uint32_t*>(Ab + base + 8 * STR_ * 2 + 16);
            }
            #pragma unroll
            for (int j = 0; j < 8; ++j) {
                int nb = ((wn * 64 + j * 8 + g) * STR_ + k0 + tq * 2) * 2;
                bh[j][0] = *reinterpret_cast<const uint32_t*>(Bhb + nb);
                bh[j][1] = *reinterpret_cast<const uint32_t*>(Bhb + nb + 16);
                bl[j][0] = *reinterpret_cast<const uint32_t*>(Blb + nb);
                bl[j][1] = *reinterpret_cast<const uint32_t*>(Blb + nb + 16);
            }
            #pragma unroll
            for (int i = 0; i < 2; ++i)
                #pragma unroll
                for (int j = 0; j < 8; ++j) {
                    MMA_F16(acc[i][j], ah[i], bh[j]);
                    MMA_F16(acc[i][j], ah[i], bl[j]);
                }
        }
        __syncthreads();
    }

    // epilogue: out = cc*(acc + bmu) + bu
    #pragma unroll
    for (int i = 0; i < 2; ++i) {
        #pragma unroll
        for (int half = 0; half < 2; ++half) {
            int lrow = wm * 32 + i * 16 + g + half * 8;
            int r    = r0 + lrow;
            if (r < M_) {
                float ccf = cc_s[lrow];
                #pragma unroll
                for (int j = 0; j < 8; ++j) {
                    int c0 = wn * 64 + j * 8 + tq * 2;
                    float2 v;
                    v.x = ccf * (acc[i][j][half * 2 + 0] + bmu_s[c0 + 0]) + bu_s[c0 + 0];
                    v.y = ccf * (acc[i][j][half * 2 + 1] + bmu_s[c0 + 1]) + bu_s[c0 + 1];
                    *reinterpret_cast<float2*>(&out[(size_t)r * 128 + c0]) = v;
                }
            }
        }
    }
}

// ---------------------------------------------------------------------------
// Launch
// ---------------------------------------------------------------------------
extern "C" void kernel_launch(void* const* d_in, const int* in_sizes, int n_in,
                              void* d_out, int out_size) {
    const float* x  = (const float*)d_in[0];   // (B, N, D)
    const int*   ei = (const int*)  d_in[1];   // (2, E)
    const float* ea = (const float*)d_in[2];   // (E, D)
    const float* Wm = (const float*)d_in[3];   // (3D, O)
    const float* bm = (const float*)d_in[4];   // (O,)
    const float* Wu = (const float*)d_in[5];   // (O, O)
    const float* bu = (const float*)d_in[6];   // (O,)
    float* out = (float*)d_out;                // (B, N, O)

    cudaFuncSetAttribute(fused_gemm_mma,
                         cudaFuncAttributeMaxDynamicSharedMemorySize, SMEM_DYN_);

    const size_t nc = (size_t)B_ * N_ * 16;
    zero_icnt<<<(N_ + 255) / 256, 256>>>();
    hist_kernel<<<(E_ + 255) / 256, 256>>>(ei);
    scan_kernel<<<1, 1024>>>();
    fill_kernel<<<(E_ + 255) / 256, 256>>>(ei);
    x_to_h<<<(unsigned)((nc + 255) / 256), 256>>>(x);
    combine_weights<<<(K_ * O_ + 255) / 256, 256>>>(Wm, Wu, bm);
    aggregate<<<(int)(((size_t)N_ * 32 + 255) / 256), 256>>>(ea);
    fused_gemm_mma<<<(M_ + 127) / 128, 256, SMEM_DYN_>>>(bu, out);
}

// round 10
// speedup vs baseline: 1.0287x; 1.0287x over previous
#include <cuda_runtime.h>
#include <cuda_fp16.h>
#include <cstdint>
#include <cstddef>

#define B_ 2
#define N_ 50000
#define E_ 500000
#define D_ 128
#define O_ 128
#define K_ 384
#define M_ (B_*N_)
#define MPAD_ (M_ + 128)

// ---------------------------------------------------------------------------
// Device scratch
// ---------------------------------------------------------------------------
__device__ __half g_A[(size_t)MPAD_ * 256];    // fp16 [inv*XS | inv*EA] (51.3MB)
__device__ __half g_xh[(size_t)B_ * N_ * D_];  // fp16 copy of x (25.6 MB)
__device__ int   g_icnt[N_];                   // in-degree counts
__device__ int   g_off[N_ + 1];                // CSR offsets by dst
__device__ int   g_pos[N_];                    // fill cursor
__device__ int2  g_edge[E_];                   // (src, edge id) sorted by dst
__device__ __half g_Bhi[O_ * K_];              // (W_msg@W_upd)^T hi, [o][k]
__device__ __half g_Blo[O_ * K_];              // (W_msg@W_upd)^T lo (residual)
__device__ float g_bmu[O_];                    // b_msg @ W_upd

// ---------------------------------------------------------------------------
// PTX helpers
// ---------------------------------------------------------------------------
#define MMA_F16(d, a, b)                                                      \
    asm volatile("mma.sync.aligned.m16n8k16.row.col.f32.f16.f16.f32 "         \
        "{%0,%1,%2,%3}, {%4,%5,%6,%7}, {%8,%9}, {%0,%1,%2,%3};"               \
        : "+f"((d)[0]), "+f"((d)[1]), "+f"((d)[2]), "+f"((d)[3])              \
        : "r"((a)[0]), "r"((a)[1]), "r"((a)[2]), "r"((a)[3]),                 \
          "r"((b)[0]), "r"((b)[1]))

#define CP_ASYNC16(dst_u32, src_ptr)                                          \
    asm volatile("cp.async.cg.shared.global [%0], [%1], 16;"                  \
                 :: "r"(dst_u32), "l"(src_ptr))
#define CP_COMMIT() asm volatile("cp.async.commit_group;" ::: "memory")
#define CP_WAIT(n)  asm volatile("cp.async.wait_group %0;" :: "n"(n) : "memory")

__device__ __forceinline__ uint32_t smem_u32(const void* p) {
    uint32_t a;
    asm("{ .reg .u64 t; cvta.to.shared.u64 t, %1; cvt.u32.u64 %0, t; }"
        : "=r"(a) : "l"(p));
    return a;
}

__device__ __forceinline__ uint4 cvt8_h(float4 f0, float4 f1) {
    uint32_t p0, p1, p2, p3;
    asm("cvt.rn.f16x2.f32 %0, %2, %1;" : "=r"(p0) : "f"(f0.x), "f"(f0.y));
    asm("cvt.rn.f16x2.f32 %0, %2, %1;" : "=r"(p1) : "f"(f0.z), "f"(f0.w));
    asm("cvt.rn.f16x2.f32 %0, %2, %1;" : "=r"(p2) : "f"(f1.x), "f"(f1.y));
    asm("cvt.rn.f16x2.f32 %0, %2, %1;" : "=r"(p3) : "f"(f1.z), "f"(f1.w));
    return make_uint4(p0, p1, p2, p3);
}
__device__ __forceinline__ uint2 cvt4_h(float4 f) {
    uint32_t p0, p1;
    asm("cvt.rn.f16x2.f32 %0, %2, %1;" : "=r"(p0) : "f"(f.x), "f"(f.y));
    asm("cvt.rn.f16x2.f32 %0, %2, %1;" : "=r"(p1) : "f"(f.z), "f"(f.w));
    return make_uint2(p0, p1);
}

// ---------------------------------------------------------------------------
// x -> fp16 copy (one uint4 = 8 values per thread)
// ---------------------------------------------------------------------------
__global__ void x_to_h(const float* __restrict__ x) {
    const size_t n8 = (size_t)B_ * N_ * D_ / 8;
    size_t i = (size_t)blockIdx.x * blockDim.x + threadIdx.x;
    if (i < n8) {
        float4 f0 = reinterpret_cast<const float4*>(x)[2 * i];
        float4 f1 = reinterpret_cast<const float4*>(x)[2 * i + 1];
        reinterpret_cast<uint4*>(g_xh)[i] = cvt8_h(f0, f1);
    }
}

// ---------------------------------------------------------------------------
// CSR build (unchanged)
// ---------------------------------------------------------------------------
__global__ void zero_icnt() {
    int i = blockIdx.x * blockDim.x + threadIdx.x;
    if (i < N_) g_icnt[i] = 0;
}

__global__ void hist_kernel(const int* __restrict__ ei) {
    int e = blockIdx.x * blockDim.x + threadIdx.x;
    if (e < E_) atomicAdd(&g_icnt[ei[E_ + e]], 1);
}

__global__ void scan_kernel() {
    __shared__ int ssum[1024];
    const int CH = (N_ + 1023) / 1024;
    int t = threadIdx.x;
    int beg = t * CH, end = min(beg + CH, N_);
    int s = 0;
    for (int i = beg; i < end; ++i) s += g_icnt[i];
    ssum[t] = s;
    __syncthreads();
    for (int off = 1; off < 1024; off <<= 1) {
        int v = (t >= off) ? ssum[t - off] : 0;
        __syncthreads();
        ssum[t] += v;
        __syncthreads();
    }
    int run = (t == 0) ? 0 : ssum[t - 1];
    for (int i = beg; i < end; ++i) {
        g_off[i] = run;
        g_pos[i] = run;
        run += g_icnt[i];
    }
    if (t == 1023) g_off[N_] = run;
}

__global__ void fill_kernel(const int* __restrict__ ei) {
    int e = blockIdx.x * blockDim.x + threadIdx.x;
    if (e < E_) {
        int dst = ei[E_ + e];
        int p = atomicAdd(&g_pos[dst], 1);
        g_edge[p] = make_int2(ei[e], e);
    }
}

// ---------------------------------------------------------------------------
// Aggregation: warp per node (R8 structure). Gathers x (fp16, two 256B rows)
// + ea (fp32), fp32 accumulate, writes g_A rows in fp16:
//   g_A[r][0:128)  = inv*XS(b)
//   g_A[r][128:256)= inv*EA
// (cc*x middle block removed — GEMM streams it straight from g_xh.)
// ---------------------------------------------------------------------------
__device__ __forceinline__ void add_h4(float4& a, uint2 h) {
    float2 lo = __half22float2(*reinterpret_cast<__half2*>(&h.x));
    float2 hi = __half22float2(*reinterpret_cast<__half2*>(&h.y));
    a.x += lo.x; a.y += lo.y; a.z += hi.x; a.w += hi.y;
}
__device__ __forceinline__ float4 scale4(float4 a, float s) {
    return make_float4(a.x * s, a.y * s, a.z * s, a.w * s);
}

__global__ void aggregate(const float* __restrict__ ea) {
    int n = (int)(((size_t)blockIdx.x * blockDim.x + threadIdx.x) >> 5);
    int lane = threadIdx.x & 31;
    if (n >= N_) return;

    int j0 = g_off[n], j1 = g_off[n + 1];
    float4 aea = make_float4(0.f, 0.f, 0.f, 0.f);
    float4 ax0 = aea, ax1 = aea;
    float4 bea = aea, bx0 = aea, bx1 = aea;

    int j = j0;
    for (; j + 2 <= j1; j += 2) {
        int2 p0 = g_edge[j];
        int2 p1 = g_edge[j + 1];
        float4 va0 = reinterpret_cast<const float4*>(ea + (size_t)p0.y * D_)[lane];
        float4 va1 = reinterpret_cast<const float4*>(ea + (size_t)p1.y * D_)[lane];
        uint2 u0 = reinterpret_cast<const uint2*>(g_xh + (size_t)p0.x * D_)[lane];
        uint2 u1 = reinterpret_cast<const uint2*>(g_xh + (size_t)p1.x * D_)[lane];
        uint2 w0 = reinterpret_cast<const uint2*>(g_xh + ((size_t)N_ + p0.x) * D_)[lane];
        uint2 w1 = reinterpret_cast<const uint2*>(g_xh + ((size_t)N_ + p1.x) * D_)[lane];
        aea.x += va0.x; aea.y += va0.y; aea.z += va0.z; aea.w += va0.w;
        bea.x += va1.x; bea.y += va1.y; bea.z += va1.z; bea.w += va1.w;
        add_h4(ax0, u0); add_h4(bx0, u1);
        add_h4(ax1, w0); add_h4(bx1, w1);
    }
    if (j < j1) {
        int2 p0 = g_edge[j];
        float4 va = reinterpret_cast<const float4*>(ea + (size_t)p0.y * D_)[lane];
        uint2 u = reinterpret_cast<const uint2*>(g_xh + (size_t)p0.x * D_)[lane];
        uint2 w = reinterpret_cast<const uint2*>(g_xh + ((size_t)N_ + p0.x) * D_)[lane];
        aea.x += va.x; aea.y += va.y; aea.z += va.z; aea.w += va.w;
        add_h4(ax0, u);
        add_h4(ax1, w);
    }
    aea.x += bea.x; aea.y += bea.y; aea.z += bea.z; aea.w += bea.w;
    ax0.x += bx0.x; ax0.y += bx0.y; ax0.z += bx0.z; ax0.w += bx0.w;
    ax1.x += bx1.x; ax1.y += bx1.y; ax1.z += bx1.z; ax1.w += bx1.w;

    int deg = j1 - j0;
    float inv = 1.0f / (float)max(deg, 1);

    __half* r0p = g_A + (size_t)n * 256;
    __half* r1p = g_A + ((size_t)N_ + n) * 256;
    uint2 eah = cvt4_h(scale4(aea, inv));
    reinterpret_cast<uint2*>(r0p)[lane]       = cvt4_h(scale4(ax0, inv)); // XS b0
    reinterpret_cast<uint2*>(r0p + 128)[lane] = eah;                      // EA
    reinterpret_cast<uint2*>(r1p)[lane]       = cvt4_h(scale4(ax1, inv)); // XS b1
    reinterpret_cast<uint2*>(r1p + 128)[lane] = eah;                      // EA
}

// ---------------------------------------------------------------------------
// Combined weights, transposed + fp16 hi/lo split (unchanged)
// ---------------------------------------------------------------------------
__global__ void combine_weights(const float* __restrict__ Wm,
                                const float* __restrict__ Wu,
                                const float* __restrict__ bm) {
    int idx = blockIdx.x * blockDim.x + threadIdx.x;
    if (idx < K_ * O_) {
        int o = idx / K_;
        int k = idx - o * K_;
        float s = 0.f;
        #pragma unroll 8
        for (int j = 0; j < O_; ++j)
            s = fmaf(Wm[k * O_ + j], Wu[j * O_ + o], s);
        __half hb = __float2half_rn(s);
        float r = s - __half2float(hb);
        g_Bhi[idx] = hb;
        g_Blo[idx] = __float2half_rn(r);
    }
    if (idx < O_) {
        float s = 0.f;
        for (int j = 0; j < O_; ++j)
            s = fmaf(bm[j], Wu[j * O_ + idx], s);
        g_bmu[idx] = s;
    }
}

// ---------------------------------------------------------------------------
// HGEMM: out[r] = cc*( A[r]@(Bhi+Blo)^T + bmu ) + bu
// A k-layout: [0:128)=g_A XS | [128:256)=g_xh (raw x) | [256:384)=g_A EA.
// CTA 128x128, BK=32, 256 thr (4m x 2n warps), warp tile 32x64,
// 2-stage cp.async pipeline (R8 proven structure).
// ---------------------------------------------------------------------------
#define STR_ 40                       // fp16 per smem row
#define TB_  (128 * STR_ * 2)         // bytes per tile buffer (10240)
#define AOF(bf)  ((bf) * TB_)
#define BHOF(bf) (2 * TB_ + (bf) * TB_)
#define BLOF(bf) (4 * TB_ + (bf) * TB_)
#define SMEM_DYN_ (6 * TB_)           // 61440

__global__ __launch_bounds__(256, 2)
void fused_gemm_mma(const float* __restrict__ bu,
                    float* __restrict__ out)
{
    extern __shared__ char sm[];
    __shared__ float cc_s[128], bmu_s[128], bu_s[128];

    const int tid  = threadIdx.x;
    const int lane = tid & 31;
    const int wid  = tid >> 5;
    const int r0   = blockIdx.x * 128;
    const int wm   = wid >> 1;        // 0..3
    const int wn   = wid & 1;         // 0..1
    const int g    = lane >> 2;       // 0..7
    const int tq   = lane & 3;        // 0..3

    const uint32_t smb = smem_u32(sm);

    if (tid < 128) {
        int r = r0 + tid;
        float cc = 0.f;
        if (r < M_) {
            int n = (r >= N_) ? (r - N_) : r;
            cc = (g_icnt[n] > 0) ? 1.f : 0.f;
        }
        cc_s[tid]  = cc;
        bmu_s[tid] = g_bmu[tid];
        bu_s[tid]  = bu[tid];
    }

    auto issue = [&](int kb, int bf) {
        #pragma unroll
        for (int t = 0; t < 2; ++t) {
            int c    = tid + t * 256;
            int row  = c >> 2;
            int col8 = (c & 3) * 8;
            uint32_t so = (uint32_t)((row * STR_ + col8) * 2);
            const __half* asrc;
            int r = r0 + row;
            if (kb < 128) {
                asrc = g_A + (size_t)r * 256 + kb + col8;
            } else if (kb < 256) {
                int rc = (r < M_) ? r : (M_ - 1);
                asrc = g_xh + (size_t)rc * 128 + (kb - 128) + col8;
            } else {
                asrc = g_A + (size_t)r * 256 + (kb - 128) + col8;
            }
            CP_ASYNC16(smb + AOF(bf)  + so, asrc);
            CP_ASYNC16(smb + BHOF(bf) + so, g_Bhi + (size_t)row * K_ + kb + col8);
            CP_ASYNC16(smb + BLOF(bf) + so, g_Blo + (size_t)row * K_ + kb + col8);
        }
        CP_COMMIT();
    };

    float acc[2][8][4];
    #pragma unroll
    for (int i = 0; i < 2; ++i)
        #pragma unroll
        for (int j = 0; j < 8; ++j)
            #pragma unroll
            for (int c = 0; c < 4; ++c) acc[i][j][c] = 0.f;

    issue(0, 0);

    const int NT = K_ / 32;  // 12
    for (int kt = 0; kt < NT; ++kt) {
        const int cur = kt & 1;
        if (kt + 1 < NT) {
            issue((kt + 1) * 32, cur ^ 1);
            CP_WAIT(1);
        } else {
            CP_WAIT(0);
        }
        __syncthreads();

        const char* Ab  = sm + AOF(cur);
        const char* Bhb = sm + BHOF(cur);
        const char* Blb = sm + BLOF(cur);

        #pragma unroll
        for (int ks = 0; ks < 2; ++ks) {
            const int k0 = ks * 16;
            uint32_t ah[2][4], bh[8][2], bl[8][2];
            #pragma unroll
            for (int i = 0; i < 2; ++i) {
                int base = ((wm * 32 + i * 16 + g) * STR_ + k0 + tq * 2) * 2;
                ah[i][0] = *reinterpret_cast<const uint32_t*>(Ab + base);
                ah[i][1] = *reinterpret_cast<const uint32_t*>(Ab + base + 8 * STR_ * 2);
                ah[i][2] = *reinterpret_cast<const uint32_t*>(Ab + base + 16);
                ah[i][3] = *reinterpret_cast<const uint32_t*>(Ab + base + 8 * STR_ * 2 + 16);
            }
            #pragma unroll
            for (int j = 0; j < 8; ++j) {
                int nb = ((wn * 64 + j * 8 + g) * STR_ + k0 + tq * 2) * 2;
                bh[j][0] = *reinterpret_cast<const uint32_t*>(Bhb + nb);
                bh[j][1] = *reinterpret_cast<const uint32_t*>(Bhb + nb + 16);
                bl[j][0] = *reinterpret_cast<const uint32_t*>(Blb + nb);
                bl[j][1] = *reinterpret_cast<const uint32_t*>(Blb + nb + 16);
            }
            #pragma unroll
            for (int i = 0; i < 2; ++i)
                #pragma unroll
                for (int j = 0; j < 8; ++j) {
                    MMA_F16(acc[i][j], ah[i], bh[j]);
                    MMA_F16(acc[i][j], ah[i], bl[j]);
                }
        }
        __syncthreads();
    }

    // epilogue: out = cc*(acc + bmu) + bu
    #pragma unroll
    for (int i = 0; i < 2; ++i) {
        #pragma unroll
        for (int half = 0; half < 2; ++half) {
            int lrow = wm * 32 + i * 16 + g + half * 8;
            int r    = r0 + lrow;
            if (r < M_) {
                float ccf = cc_s[lrow];
                #pragma unroll
                for (int j = 0; j < 8; ++j) {
                    int c0 = wn * 64 + j * 8 + tq * 2;
                    float2 v;
                    v.x = ccf * (acc[i][j][half * 2 + 0] + bmu_s[c0 + 0]) + bu_s[c0 + 0];
                    v.y = ccf * (acc[i][j][half * 2 + 1] + bmu_s[c0 + 1]) + bu_s[c0 + 1];
                    *reinterpret_cast<float2*>(&out[(size_t)r * 128 + c0]) = v;
                }
            }
        }
    }
}

// ---------------------------------------------------------------------------
// Launch
// ---------------------------------------------------------------------------
extern "C" void kernel_launch(void* const* d_in, const int* in_sizes, int n_in,
                              void* d_out, int out_size) {
    const float* x  = (const float*)d_in[0];   // (B, N, D)
    const int*   ei = (const int*)  d_in[1];   // (2, E)
    const float* ea = (const float*)d_in[2];   // (E, D)
    const float* Wm = (const float*)d_in[3];   // (3D, O)
    const float* bm = (const float*)d_in[4];   // (O,)
    const float* Wu = (const float*)d_in[5];   // (O, O)
    const float* bu = (const float*)d_in[6];   // (O,)
    float* out = (float*)d_out;                // (B, N, O)

    cudaFuncSetAttribute(fused_gemm_mma,
                         cudaFuncAttributeMaxDynamicSharedMemorySize, SMEM_DYN_);

    const size_t n8 = (size_t)B_ * N_ * D_ / 8;
    zero_icnt<<<(N_ + 255) / 256, 256>>>();
    hist_kernel<<<(E_ + 255) / 256, 256>>>(ei);
    scan_kernel<<<1, 1024>>>();
    fill_kernel<<<(E_ + 255) / 256, 256>>>(ei);
    x_to_h<<<(unsigned)((n8 + 255) / 256), 256>>>(x);
    combine_weights<<<(K_ * O_ + 255) / 256, 256>>>(Wm, Wu, bm);
    aggregate<<<(int)(((size_t)N_ * 32 + 255) / 256), 256>>>(ea);
    fused_gemm_mma<<<(M_ + 127) / 128, 256, SMEM_DYN_>>>(bu, out);
}

// round 11
// speedup vs baseline: 1.0876x; 1.0573x over previous
#include <cuda_runtime.h>
#include <cuda_fp16.h>
#include <cstdint>
#include <cstddef>

#define B_ 2
#define N_ 50000
#define E_ 500000
#define D_ 128
#define O_ 128
#define K_ 384
#define M_ (B_*N_)
#define MPAD_ (M_ + 128)

// ---------------------------------------------------------------------------
// Device scratch
// ---------------------------------------------------------------------------
__device__ __half g_A[(size_t)MPAD_ * 256];    // fp16 [inv*XS | inv*EA] (51.3MB)
__device__ __half g_xh[(size_t)B_ * N_ * D_];  // fp16 copy of x (25.6 MB)
__device__ int   g_icnt[N_];                   // in-degree counts
__device__ int   g_off[N_ + 1];                // CSR offsets by dst
__device__ int   g_pos[N_];                    // fill cursor
__device__ int2  g_edge[E_];                   // (src, edge id) sorted by dst
__device__ __half g_Bhi[O_ * K_];              // (W_msg@W_upd)^T hi, [o][k]
__device__ __half g_Blo[O_ * K_];              // (W_msg@W_upd)^T lo (residual)
__device__ float g_bmu[O_];                    // b_msg @ W_upd

// ---------------------------------------------------------------------------
// PTX helpers
// ---------------------------------------------------------------------------
#define MMA_F16(d, a, b)                                                      \
    asm volatile("mma.sync.aligned.m16n8k16.row.col.f32.f16.f16.f32 "         \
        "{%0,%1,%2,%3}, {%4,%5,%6,%7}, {%8,%9}, {%0,%1,%2,%3};"               \
        : "+f"((d)[0]), "+f"((d)[1]), "+f"((d)[2]), "+f"((d)[3])              \
        : "r"((a)[0]), "r"((a)[1]), "r"((a)[2]), "r"((a)[3]),                 \
          "r"((b)[0]), "r"((b)[1]))

#define CP_ASYNC16(dst_u32, src_ptr)                                          \
    asm volatile("cp.async.cg.shared.global [%0], [%1], 16;"                  \
                 :: "r"(dst_u32), "l"(src_ptr))
#define CP_ASYNC8(dst_u32, src_ptr)                                           \
    asm volatile("cp.async.ca.shared.global [%0], [%1], 8;"                   \
                 :: "r"(dst_u32), "l"(src_ptr))
#define CP_COMMIT() asm volatile("cp.async.commit_group;" ::: "memory")
#define CP_WAIT(n)  asm volatile("cp.async.wait_group %0;" :: "n"(n) : "memory")

__device__ __forceinline__ uint32_t smem_u32(const void* p) {
    uint32_t a;
    asm("{ .reg .u64 t; cvta.to.shared.u64 t, %1; cvt.u32.u64 %0, t; }"
        : "=r"(a) : "l"(p));
    return a;
}

__device__ __forceinline__ uint4 cvt8_h(float4 f0, float4 f1) {
    uint32_t p0, p1, p2, p3;
    asm("cvt.rn.f16x2.f32 %0, %2, %1;" : "=r"(p0) : "f"(f0.x), "f"(f0.y));
    asm("cvt.rn.f16x2.f32 %0, %2, %1;" : "=r"(p1) : "f"(f0.z), "f"(f0.w));
    asm("cvt.rn.f16x2.f32 %0, %2, %1;" : "=r"(p2) : "f"(f1.x), "f"(f1.y));
    asm("cvt.rn.f16x2.f32 %0, %2, %1;" : "=r"(p3) : "f"(f1.z), "f"(f1.w));
    return make_uint4(p0, p1, p2, p3);
}
__device__ __forceinline__ uint2 cvt4_h(float4 f) {
    uint32_t p0, p1;
    asm("cvt.rn.f16x2.f32 %0, %2, %1;" : "=r"(p0) : "f"(f.x), "f"(f.y));
    asm("cvt.rn.f16x2.f32 %0, %2, %1;" : "=r"(p1) : "f"(f.z), "f"(f.w));
    return make_uint2(p0, p1);
}

// ---------------------------------------------------------------------------
// x -> fp16 copy (one uint4 = 8 values per thread)
// ---------------------------------------------------------------------------
__global__ void x_to_h(const float* __restrict__ x) {
    const size_t n8 = (size_t)B_ * N_ * D_ / 8;
    size_t i = (size_t)blockIdx.x * blockDim.x + threadIdx.x;
    if (i < n8) {
        float4 f0 = reinterpret_cast<const float4*>(x)[2 * i];
        float4 f1 = reinterpret_cast<const float4*>(x)[2 * i + 1];
        reinterpret_cast<uint4*>(g_xh)[i] = cvt8_h(f0, f1);
    }
}

// ---------------------------------------------------------------------------
// CSR build (unchanged)
// ---------------------------------------------------------------------------
__global__ void zero_icnt() {
    int i = blockIdx.x * blockDim.x + threadIdx.x;
    if (i < N_) g_icnt[i] = 0;
}

__global__ void hist_kernel(const int* __restrict__ ei) {
    int e = blockIdx.x * blockDim.x + threadIdx.x;
    if (e < E_) atomicAdd(&g_icnt[ei[E_ + e]], 1);
}

__global__ void scan_kernel() {
    __shared__ int ssum[1024];
    const int CH = (N_ + 1023) / 1024;
    int t = threadIdx.x;
    int beg = t * CH, end = min(beg + CH, N_);
    int s = 0;
    for (int i = beg; i < end; ++i) s += g_icnt[i];
    ssum[t] = s;
    __syncthreads();
    for (int off = 1; off < 1024; off <<= 1) {
        int v = (t >= off) ? ssum[t - off] : 0;
        __syncthreads();
        ssum[t] += v;
        __syncthreads();
    }
    int run = (t == 0) ? 0 : ssum[t - 1];
    for (int i = beg; i < end; ++i) {
        g_off[i] = run;
        g_pos[i] = run;
        run += g_icnt[i];
    }
    if (t == 1023) g_off[N_] = run;
}

__global__ void fill_kernel(const int* __restrict__ ei) {
    int e = blockIdx.x * blockDim.x + threadIdx.x;
    if (e < E_) {
        int dst = ei[E_ + e];
        int p = atomicAdd(&g_pos[dst], 1);
        g_edge[p] = make_int2(ei[e], e);
    }
}

// ---------------------------------------------------------------------------
// Aggregation with cp.async pipeline: warp per node, 4-slot ring buffer.
// Per edge slot (1KB): [0:512) ea fp32 row, [512:768) x b0 fp16 row,
// [768:1024) x b1 fp16 row. One commit-group per edge; wait_group 3 gives a
// guaranteed 4-edge / 12-load lookahead decoupled from the FADD chain.
// Each lane reads exactly the bytes its own cp.async wrote (no barrier).
// Writes g_A rows: [0:128)=inv*XS(b), [128:256)=inv*EA.
// ---------------------------------------------------------------------------
__device__ __forceinline__ void add_h4(float4& a, uint2 h) {
    float2 lo = __half22float2(*reinterpret_cast<__half2*>(&h.x));
    float2 hi = __half22float2(*reinterpret_cast<__half2*>(&h.y));
    a.x += lo.x; a.y += lo.y; a.z += hi.x; a.w += hi.y;
}
__device__ __forceinline__ float4 scale4(float4 a, float s) {
    return make_float4(a.x * s, a.y * s, a.z * s, a.w * s);
}

__global__ __launch_bounds__(256)
void aggregate(const float* __restrict__ ea) {
    __shared__ char pipes[8 * 4 * 1024];   // 8 warps x 4 slots x 1KB

    const int tid  = threadIdx.x;
    const int wid  = tid >> 5;
    const int lane = tid & 31;
    int n = (int)(((size_t)blockIdx.x * blockDim.x + tid) >> 5);
    if (n >= N_) return;

    char* wp = pipes + wid * 4096;
    const uint32_t wb = smem_u32(wp);

    const int j0 = g_off[n], j1 = g_off[n + 1];
    float4 ae = make_float4(0.f, 0.f, 0.f, 0.f);
    float4 xa = ae, xb = ae;

    for (int c = j0; c < j1; c += 32) {
        const int cnt = min(32, j1 - c);
        int2 myp = make_int2(0, 0);
        if (lane < cnt) myp = g_edge[c + lane];

        // prologue: 4 commit-groups (pad with empty groups if cnt < 4)
        #pragma unroll
        for (int i = 0; i < 4; ++i) {
            if (i < cnt) {
                int src = __shfl_sync(0xffffffffu, myp.x, i);
                int eid = __shfl_sync(0xffffffffu, myp.y, i);
                uint32_t so = wb + i * 1024;
                CP_ASYNC16(so + lane * 16, ea + (size_t)eid * D_ + lane * 4);
                CP_ASYNC8(so + 512 + lane * 8, g_xh + (size_t)src * D_ + lane * 4);
                CP_ASYNC8(so + 768 + lane * 8, g_xh + ((size_t)N_ + src) * D_ + lane * 4);
            }
            CP_COMMIT();
        }

        for (int d = 0; d < cnt; ++d) {
            CP_WAIT(3);                     // edge d's group retired
            const char* sp = wp + (d & 3) * 1024;
            float4 va = *reinterpret_cast<const float4*>(sp + lane * 16);
            uint2  u  = *reinterpret_cast<const uint2*>(sp + 512 + lane * 8);
            uint2  w  = *reinterpret_cast<const uint2*>(sp + 768 + lane * 8);
            ae.x += va.x; ae.y += va.y; ae.z += va.z; ae.w += va.w;
            add_h4(xa, u);
            add_h4(xb, w);

            int nx = d + 4;
            if (nx < cnt) {
                int src = __shfl_sync(0xffffffffu, myp.x, nx);
                int eid = __shfl_sync(0xffffffffu, myp.y, nx);
                uint32_t so = wb + (nx & 3) * 1024;
                CP_ASYNC16(so + lane * 16, ea + (size_t)eid * D_ + lane * 4);
                CP_ASYNC8(so + 512 + lane * 8, g_xh + (size_t)src * D_ + lane * 4);
                CP_ASYNC8(so + 768 + lane * 8, g_xh + ((size_t)N_ + src) * D_ + lane * 4);
            }
            CP_COMMIT();
        }
    }

    const int deg = j1 - j0;
    const float inv = 1.0f / (float)max(deg, 1);

    __half* r0p = g_A + (size_t)n * 256;
    __half* r1p = g_A + ((size_t)N_ + n) * 256;
    uint2 eah = cvt4_h(scale4(ae, inv));
    reinterpret_cast<uint2*>(r0p)[lane]       = cvt4_h(scale4(xa, inv)); // XS b0
    reinterpret_cast<uint2*>(r0p + 128)[lane] = eah;                     // EA
    reinterpret_cast<uint2*>(r1p)[lane]       = cvt4_h(scale4(xb, inv)); // XS b1
    reinterpret_cast<uint2*>(r1p + 128)[lane] = eah;                     // EA
}

// ---------------------------------------------------------------------------
// Combined weights, transposed + fp16 hi/lo split (unchanged)
// ---------------------------------------------------------------------------
__global__ void combine_weights(const float* __restrict__ Wm,
                                const float* __restrict__ Wu,
                                const float* __restrict__ bm) {
    int idx = blockIdx.x * blockDim.x + threadIdx.x;
    if (idx < K_ * O_) {
        int o = idx / K_;
        int k = idx - o * K_;
        float s = 0.f;
        #pragma unroll 8
        for (int j = 0; j < O_; ++j)
            s = fmaf(Wm[k * O_ + j], Wu[j * O_ + o], s);
        __half hb = __float2half_rn(s);
        float r = s - __half2float(hb);
        g_Bhi[idx] = hb;
        g_Blo[idx] = __float2half_rn(r);
    }
    if (idx < O_) {
        float s = 0.f;
        for (int j = 0; j < O_; ++j)
            s = fmaf(bm[j], Wu[j * O_ + idx], s);
        g_bmu[idx] = s;
    }
}

// ---------------------------------------------------------------------------
// HGEMM: out[r] = cc*( A[r]@(Bhi+Blo)^T + bmu ) + bu   (unchanged from R10)
// A k-layout: [0:128)=g_A XS | [128:256)=g_xh (raw x) | [256:384)=g_A EA.
// ---------------------------------------------------------------------------
#define STR_ 40                       // fp16 per smem row
#define TB_  (128 * STR_ * 2)         // bytes per tile buffer (10240)
#define AOF(bf)  ((bf) * TB_)
#define BHOF(bf) (2 * TB_ + (bf) * TB_)
#define BLOF(bf) (4 * TB_ + (bf) * TB_)
#define SMEM_DYN_ (6 * TB_)           // 61440

__global__ __launch_bounds__(256, 2)
void fused_gemm_mma(const float* __restrict__ bu,
                    float* __restrict__ out)
{
    extern __shared__ char sm[];
    __shared__ float cc_s[128], bmu_s[128], bu_s[128];

    const int tid  = threadIdx.x;
    const int lane = tid & 31;
    const int wid  = tid >> 5;
    const int r0   = blockIdx.x * 128;
    const int wm   = wid >> 1;        // 0..3
    const int wn   = wid & 1;         // 0..1
    const int g    = lane >> 2;       // 0..7
    const int tq   = lane & 3;        // 0..3

    const uint32_t smb = smem_u32(sm);

    if (tid < 128) {
        int r = r0 + tid;
        float cc = 0.f;
        if (r < M_) {
            int n = (r >= N_) ? (r - N_) : r;
            cc = (g_icnt[n] > 0) ? 1.f : 0.f;
        }
        cc_s[tid]  = cc;
        bmu_s[tid] = g_bmu[tid];
        bu_s[tid]  = bu[tid];
    }

    auto issue = [&](int kb, int bf) {
        #pragma unroll
        for (int t = 0; t < 2; ++t) {
            int c    = tid + t * 256;
            int row  = c >> 2;
            int col8 = (c & 3) * 8;
            uint32_t so = (uint32_t)((row * STR_ + col8) * 2);
            const __half* asrc;
            int r = r0 + row;
            if (kb < 128) {
                asrc = g_A + (size_t)r * 256 + kb + col8;
            } else if (kb < 256) {
                int rc = (r < M_) ? r : (M_ - 1);
                asrc = g_xh + (size_t)rc * 128 + (kb - 128) + col8;
            } else {
                asrc = g_A + (size_t)r * 256 + (kb - 128) + col8;
            }
            CP_ASYNC16(smb + AOF(bf)  + so, asrc);
            CP_ASYNC16(smb + BHOF(bf) + so, g_Bhi + (size_t)row * K_ + kb + col8);
            CP_ASYNC16(smb + BLOF(bf) + so, g_Blo + (size_t)row * K_ + kb + col8);
        }
        CP_COMMIT();
    };

    float acc[2][8][4];
    #pragma unroll
    for (int i = 0; i < 2; ++i)
        #pragma unroll
        for (int j = 0; j < 8; ++j)
            #pragma unroll
            for (int c = 0; c < 4; ++c) acc[i][j][c] = 0.f;

    issue(0, 0);

    const int NT = K_ / 32;  // 12
    for (int kt = 0; kt < NT; ++kt) {
        const int cur = kt & 1;
        if (kt + 1 < NT) {
            issue((kt + 1) * 32, cur ^ 1);
            CP_WAIT(1);
        } else {
            CP_WAIT(0);
        }
        __syncthreads();

        const char* Ab  = sm + AOF(cur);
        const char* Bhb = sm + BHOF(cur);
        const char* Blb = sm + BLOF(cur);

        #pragma unroll
        for (int ks = 0; ks < 2; ++ks) {
            const int k0 = ks * 16;
            uint32_t ah[2][4], bh[8][2], bl[8][2];
            #pragma unroll
            for (int i = 0; i < 2; ++i) {
                int base = ((wm * 32 + i * 16 + g) * STR_ + k0 + tq * 2) * 2;
                ah[i][0] = *reinterpret_cast<const uint32_t*>(Ab + base);
                ah[i][1] = *reinterpret_cast<const uint32_t*>(Ab + base + 8 * STR_ * 2);
                ah[i][2] = *reinterpret_cast<const uint32_t*>(Ab + base + 16);
                ah[i][3] = *reinterpret_cast<const uint32_t*>(Ab + base + 8 * STR_ * 2 + 16);
            }
            #pragma unroll
            for (int j = 0; j < 8; ++j) {
                int nb = ((wn * 64 + j * 8 + g) * STR_ + k0 + tq * 2) * 2;
                bh[j][0] = *reinterpret_cast<const uint32_t*>(Bhb + nb);
                bh[j][1] = *reinterpret_cast<const uint32_t*>(Bhb + nb + 16);
                bl[j][0] = *reinterpret_cast<const uint32_t*>(Blb + nb);
                bl[j][1] = *reinterpret_cast<const uint32_t*>(Blb + nb + 16);
            }
            #pragma unroll
            for (int i = 0; i < 2; ++i)
                #pragma unroll
                for (int j = 0; j < 8; ++j) {
                    MMA_F16(acc[i][j], ah[i], bh[j]);
                    MMA_F16(acc[i][j], ah[i], bl[j]);
                }
        }
        __syncthreads();
    }

    // epilogue: out = cc*(acc + bmu) + bu
    #pragma unroll
    for (int i = 0; i < 2; ++i) {
        #pragma unroll
        for (int half = 0; half < 2; ++half) {
            int lrow = wm * 32 + i * 16 + g + half * 8;
            int r    = r0 + lrow;
            if (r < M_) {
                float ccf = cc_s[lrow];
                #pragma unroll
                for (int j = 0; j < 8; ++j) {
                    int c0 = wn * 64 + j * 8 + tq * 2;
                    float2 v;
                    v.x = ccf * (acc[i][j][half * 2 + 0] + bmu_s[c0 + 0]) + bu_s[c0 + 0];
                    v.y = ccf * (acc[i][j][half * 2 + 1] + bmu_s[c0 + 1]) + bu_s[c0 + 1];
                    *reinterpret_cast<float2*>(&out[(size_t)r * 128 + c0]) = v;
                }
            }
        }
    }
}

// ---------------------------------------------------------------------------
// Launch
// ---------------------------------------------------------------------------
extern "C" void kernel_launch(void* const* d_in, const int* in_sizes, int n_in,
                              void* d_out, int out_size) {
    const float* x  = (const float*)d_in[0];   // (B, N, D)
    const int*   ei = (const int*)  d_in[1];   // (2, E)
    const float* ea = (const float*)d_in[2];   // (E, D)
    const float* Wm = (const float*)d_in[3];   // (3D, O)
    const float* bm = (const float*)d_in[4];   // (O,)
    const float* Wu = (const float*)d_in[5];   // (O, O)
    const float* bu = (const float*)d_in[6];   // (O,)
    float* out = (float*)d_out;                // (B, N, O)

    cudaFuncSetAttribute(fused_gemm_mma,
                         cudaFuncAttributeMaxDynamicSharedMemorySize, SMEM_DYN_);

    const size_t n8 = (size_t)B_ * N_ * D_ / 8;
    zero_icnt<<<(N_ + 255) / 256, 256>>>();
    hist_kernel<<<(E_ + 255) / 256, 256>>>(ei);
    scan_kernel<<<1, 1024>>>();
    fill_kernel<<<(E_ + 255) / 256, 256>>>(ei);
    x_to_h<<<(unsigned)((n8 + 255) / 256), 256>>>(x);
    combine_weights<<<(K_ * O_ + 255) / 256, 256>>>(Wm, Wu, bm);
    aggregate<<<(int)(((size_t)N_ * 32 + 255) / 256), 256>>>(ea);
    fused_gemm_mma<<<(M_ + 127) / 128, 256, SMEM_DYN_>>>(bu, out);
}